// round 1
// baseline (speedup 1.0000x reference)
#include <cuda_runtime.h>

#define NODES 2048
#define EDGES 65536
#define D     128
#define EPSF  1e-6f

// ---------------- scratch (no allocation allowed) ----------------
__device__ float    g_P[NODES * D];      // x @ fW[:128,:]
__device__ float    g_Q[NODES * D];      // x @ fW[128:,:]
__device__ float    g_s[NODES];          // x @ wW[:128]
__device__ float    g_t[NODES];          // x @ wW[128:]
__device__ int      g_counts[NODES];
__device__ int      g_offsets[NODES + 1];
__device__ int      g_cursor[NODES];
__device__ int      g_edge_src[EDGES];
__device__ unsigned g_amax_key;

// order-preserving float <-> uint mapping (for atomicMax over floats)
__device__ __forceinline__ unsigned fkey(float f) {
    unsigned b = __float_as_uint(f);
    return (b & 0x80000000u) ? ~b : (b | 0x80000000u);
}
__device__ __forceinline__ float funkey(unsigned u) {
    return __uint_as_float((u & 0x80000000u) ? (u ^ 0x80000000u) : ~u);
}

// ---------------- kernels ----------------

__global__ void k_init() {
    int i = blockIdx.x * blockDim.x + threadIdx.x;
    if (i < NODES) g_counts[i] = 0;
    if (i == 0) g_amax_key = 0u;   // decodes to "smaller than any float"
}

// One block per node: P[n,:], Q[n,:], s[n], t[n]
__global__ void k_precompute(const float* __restrict__ x,
                             const float* __restrict__ fW,
                             const float* __restrict__ wW) {
    __shared__ float xs[D];
    __shared__ float red[D];
    int n = blockIdx.x, j = threadIdx.x;
    xs[j] = x[n * D + j];
    __syncthreads();

    float p = 0.f, q = 0.f;
#pragma unroll 8
    for (int k = 0; k < D; k++) {
        float xv = xs[k];
        p = fmaf(xv, fW[k * D + j], p);
        q = fmaf(xv, fW[(k + D) * D + j], q);
    }
    g_P[n * D + j] = p;
    g_Q[n * D + j] = q;

    // s[n] = sum_k x[n,k]*wW[k];  t[n] = sum_k x[n,k]*wW[128+k]
    float ps = xs[j] * wW[j];
    float pt = xs[j] * wW[D + j];

    red[j] = ps; __syncthreads();
    for (int o = 64; o > 0; o >>= 1) {
        if (j < o) red[j] += red[j + o];
        __syncthreads();
    }
    if (j == 0) g_s[n] = red[0];
    __syncthreads();
    red[j] = pt; __syncthreads();
    for (int o = 64; o > 0; o >>= 1) {
        if (j < o) red[j] += red[j + o];
        __syncthreads();
    }
    if (j == 0) g_t[n] = red[0];
}

// histogram of tgt + global max of (s[src]+t[tgt])  (the +wb cancels in softmax)
__global__ void k_histmax(const int* __restrict__ src,
                          const int* __restrict__ tgt, int E) {
    int e = blockIdx.x * blockDim.x + threadIdx.x;
    float a = -3.4e38f;
    if (e < E) {
        atomicAdd(&g_counts[tgt[e]], 1);
        a = g_s[src[e]] + g_t[tgt[e]];
    }
#pragma unroll
    for (int o = 16; o > 0; o >>= 1)
        a = fmaxf(a, __shfl_xor_sync(0xFFFFFFFFu, a, o));
    __shared__ float wmax[8];
    int wid = threadIdx.x >> 5;
    if ((threadIdx.x & 31) == 0) wmax[wid] = a;
    __syncthreads();
    if (threadIdx.x == 0) {
        float m = wmax[0];
        for (int i = 1; i < (int)(blockDim.x >> 5); i++) m = fmaxf(m, wmax[i]);
        atomicMax(&g_amax_key, fkey(m));
    }
}

// exclusive scan of counts[2048] in one 1024-thread block
__global__ void k_scan(int E) {
    __shared__ int sh[1024];
    int t = threadIdx.x;
    int c0 = g_counts[2 * t];
    int c1 = g_counts[2 * t + 1];
    sh[t] = c0 + c1;
    __syncthreads();
    for (int off = 1; off < 1024; off <<= 1) {
        int v = sh[t];
        int add = (t >= off) ? sh[t - off] : 0;
        __syncthreads();
        sh[t] = v + add;
        __syncthreads();
    }
    int excl = (t > 0) ? sh[t - 1] : 0;       // exclusive prefix of the pairs
    g_offsets[2 * t]     = excl;
    g_offsets[2 * t + 1] = excl + c0;
    g_cursor[2 * t]      = excl;
    g_cursor[2 * t + 1]  = excl + c0;
    if (t == 0) g_offsets[NODES] = E;
}

// bucket edges by target; store only src id (all we need downstream)
__global__ void k_scatter(const int* __restrict__ src,
                          const int* __restrict__ tgt, int E) {
    int e = blockIdx.x * blockDim.x + threadIdx.x;
    if (e < E) {
        int pos = atomicAdd(&g_cursor[tgt[e]], 1);
        g_edge_src[pos] = src[e];
    }
}

// One block per target node: register accumulation, no atomics.
__global__ void k_aggregate(float* __restrict__ out,
                            const float* __restrict__ fb) {
    int n = blockIdx.x, j = threadIdx.x;
    int b = g_offsets[n];
    int e = g_offsets[n + 1];
    float M  = funkey(g_amax_key);
    float tn = g_t[n];
    float qf = g_Q[n * D + j] + fb[j];   // loop-invariant

    float acc = 0.f, asum = 0.f;
#pragma unroll 4
    for (int i = b; i < e; i++) {
        int sid = g_edge_src[i];
        float w = __expf(g_s[sid] + tn - M);         // a_exp (wb cancels)
        float v = g_P[sid * D + j] + qf;             // pre-relu message
        acc  = fmaf(fmaxf(v, 0.f), w, acc);
        asum += w;
    }
    out[n * D + j] = acc / (asum + EPSF);
}

// ---------------- launch ----------------
extern "C" void kernel_launch(void* const* d_in, const int* in_sizes, int n_in,
                              void* d_out, int out_size) {
    const float* x   = (const float*)d_in[0];
    const int*   src = (const int*)  d_in[2];
    const int*   tgt = (const int*)  d_in[3];
    const float* fW  = (const float*)d_in[6];
    const float* fb  = (const float*)d_in[7];
    const float* wW  = (const float*)d_in[8];
    float*       out = (float*)d_out;

    int E = in_sizes[2];              // 65536
    int N = in_sizes[0] / D;          // 2048

    k_init<<<(N + 255) / 256, 256>>>();
    k_precompute<<<N, D>>>(x, fW, wW);
    k_histmax<<<(E + 255) / 256, 256>>>(src, tgt, E);
    k_scan<<<1, 1024>>>(E);
    k_scatter<<<(E + 255) / 256, 256>>>(src, tgt, E);
    k_aggregate<<<N, D>>>(out, fb);
}

// round 3
// speedup vs baseline: 1.1012x; 1.1012x over previous
#include <cuda_runtime.h>

#define NODES 2048
#define EDGES 65536
#define D     128
#define NB    16          // nodes per precompute block
#define CHUNK 256
#define EPSF  1e-6f

// ---------------- scratch (no allocation allowed) ----------------
struct __align__(16) Meta { int counts[NODES]; unsigned amax; };
__device__ Meta g_meta;
__device__ __align__(16) float g_P[NODES * D];   // x @ fW[:128,:]
__device__ __align__(16) float g_Q[NODES * D];   // x @ fW[128:,:]
__device__ float g_s[NODES];
__device__ float g_t[NODES];
__device__ __align__(16) int g_offsets[NODES + 1];
__device__ __align__(16) int g_cursor[NODES];
__device__ int g_edge_src[EDGES];

// order-preserving float <-> uint (atomicMax over floats); key 0 < any real key
__device__ __forceinline__ unsigned fkey(float f) {
    unsigned b = __float_as_uint(f);
    return (b & 0x80000000u) ? ~b : (b | 0x80000000u);
}
__device__ __forceinline__ float funkey(unsigned u) {
    return __uint_as_float((u & 0x80000000u) ? (u ^ 0x80000000u) : ~u);
}

// ---------------- kernel 1: GEMM tiles + s,t + tgt histogram ----------------
__global__ __launch_bounds__(256) void k_pre(const float* __restrict__ x,
                                             const float* __restrict__ fW,
                                             const float* __restrict__ wW,
                                             const int* __restrict__ tgt) {
    __shared__ float xs[D][NB + 2];   // k-major, padded so rows stay 8B-aligned
    __shared__ float wWs[2 * D];
    __shared__ float red[128];
    int tid = threadIdx.x;
    int nb  = blockIdx.x * NB;

    // fused tgt histogram: 512 edges per block (hidden behind the GEMM)
    int e0 = blockIdx.x * (EDGES / (NODES / NB));
    atomicAdd(&g_meta.counts[tgt[e0 + tid]], 1);
    atomicAdd(&g_meta.counts[tgt[e0 + tid + 256]], 1);

    // stage x transposed (16 nodes x 128 feats) + wW
    for (int i = tid; i < NB * D; i += 256) {
        int n = i >> 7, k = i & 127;
        xs[k][n] = x[(nb + n) * D + k];
    }
    wWs[tid] = wW[tid];
    __syncthreads();

    // each thread: output column j, 8 nodes, packed as 4 f32x2 accumulators per half
    int j = tid & 127, g = tid >> 7;
    int xbase = g * 8;
    const float* fwp = fW + j;
    const float* fwq = fW + D * D + j;
    unsigned long long ap0=0,ap1=0,ap2=0,ap3=0,aq0=0,aq1=0,aq2=0,aq3=0;

#pragma unroll 4
    for (int k = 0; k < D; k++) {
        float wp = __ldg(fwp + k * D);
        float wq = __ldg(fwq + k * D);
        unsigned long long wpp, wqq;
        asm("mov.b64 %0,{%1,%1};" : "=l"(wpp) : "f"(wp));
        asm("mov.b64 %0,{%1,%1};" : "=l"(wqq) : "f"(wq));
        const unsigned long long* xr =
            reinterpret_cast<const unsigned long long*>(&xs[k][xbase]);
        unsigned long long x0 = xr[0], x1 = xr[1], x2 = xr[2], x3 = xr[3];
        asm("fma.rn.f32x2 %0,%1,%2,%0;" : "+l"(ap0) : "l"(x0), "l"(wpp));
        asm("fma.rn.f32x2 %0,%1,%2,%0;" : "+l"(ap1) : "l"(x1), "l"(wpp));
        asm("fma.rn.f32x2 %0,%1,%2,%0;" : "+l"(ap2) : "l"(x2), "l"(wpp));
        asm("fma.rn.f32x2 %0,%1,%2,%0;" : "+l"(ap3) : "l"(x3), "l"(wpp));
        asm("fma.rn.f32x2 %0,%1,%2,%0;" : "+l"(aq0) : "l"(x0), "l"(wqq));
        asm("fma.rn.f32x2 %0,%1,%2,%0;" : "+l"(aq1) : "l"(x1), "l"(wqq));
        asm("fma.rn.f32x2 %0,%1,%2,%0;" : "+l"(aq2) : "l"(x2), "l"(wqq));
        asm("fma.rn.f32x2 %0,%1,%2,%0;" : "+l"(aq3) : "l"(x3), "l"(wqq));
    }

    float lo, hi;
#define STORE_PAIR(dst, acc, i) \
    asm("mov.b64 {%0,%1},%2;" : "=f"(lo), "=f"(hi) : "l"(acc)); \
    dst[(nb + xbase + 2*(i)    ) * D + j] = lo; \
    dst[(nb + xbase + 2*(i) + 1) * D + j] = hi;
    STORE_PAIR(g_P, ap0, 0) STORE_PAIR(g_P, ap1, 1)
    STORE_PAIR(g_P, ap2, 2) STORE_PAIR(g_P, ap3, 3)
    STORE_PAIR(g_Q, aq0, 0) STORE_PAIR(g_Q, aq1, 1)
    STORE_PAIR(g_Q, aq2, 2) STORE_PAIR(g_Q, aq3, 3)
#undef STORE_PAIR

    // s,t: 128 threads, (node, half, k-quarter) split, then reduce
    if (tid < 128) {
        int n = tid & 15, half = (tid >> 4) & 1, q = tid >> 5;
        const float* wv = wWs + half * D;
        float p = 0.f;
#pragma unroll 8
        for (int k = q * 32; k < q * 32 + 32; k++) p = fmaf(xs[k][n], wv[k], p);
        red[tid] = p;
    }
    __syncthreads();
    if (tid < 32) {
        float v = red[tid] + red[tid + 32] + red[tid + 64] + red[tid + 96];
        int n = tid & 15, half = tid >> 4;
        if (half) g_t[nb + n] = v; else g_s[nb + n] = v;
    }
}

// ---------------- kernel 2: warp-shuffle scan of counts ----------------
__global__ __launch_bounds__(512) void k_scan() {
    __shared__ int wsum[16];
    int t = threadIdx.x, lane = t & 31, wid = t >> 5;
    int4 c = reinterpret_cast<const int4*>(g_meta.counts)[t];
    int S = c.x + c.y + c.z + c.w;
    int v = S;
#pragma unroll
    for (int o = 1; o < 32; o <<= 1) {
        int u = __shfl_up_sync(0xffffffffu, v, o);
        if (lane >= o) v += u;
    }
    if (lane == 31) wsum[wid] = v;
    __syncthreads();
    if (wid == 0) {
        int w = (lane < 16) ? wsum[lane] : 0;
#pragma unroll
        for (int o = 1; o < 16; o <<= 1) {
            int u = __shfl_up_sync(0xffffffffu, w, o);
            if (lane >= o) w += u;
        }
        if (lane < 16) wsum[lane] = w;
    }
    __syncthreads();
    int base = (wid ? wsum[wid - 1] : 0) + (v - S);   // exclusive prefix
    int4 off;
    off.x = base; off.y = base + c.x; off.z = off.y + c.y; off.w = off.z + c.z;
    reinterpret_cast<int4*>(g_offsets)[t] = off;
    reinterpret_cast<int4*>(g_cursor)[t]  = off;
    if (t == 0) g_offsets[NODES] = EDGES;
}

// ---------------- kernel 3: bucket edges by target + EXACT global max ----------------
__global__ __launch_bounds__(256) void k_scatter(const int* __restrict__ src,
                                                 const int* __restrict__ tgt) {
    int e = blockIdx.x * blockDim.x + threadIdx.x;
    int s = src[e], t = tgt[e];
    int pos = atomicAdd(&g_cursor[t], 1);
    g_edge_src[pos] = s;

    float a = g_s[s] + g_t[t];            // logit minus wb (wb cancels in softmax)
#pragma unroll
    for (int o = 16; o > 0; o >>= 1)
        a = fmaxf(a, __shfl_xor_sync(0xffffffffu, a, o));
    __shared__ float wmax[8];
    int lane = threadIdx.x & 31, wid = threadIdx.x >> 5;
    if (lane == 0) wmax[wid] = a;
    __syncthreads();
    if (threadIdx.x == 0) {
        float m = wmax[0];
#pragma unroll
        for (int i = 1; i < 8; i++) m = fmaxf(m, wmax[i]);
        atomicMax(&g_meta.amax, fkey(m));
    }
}

// ---------------- kernel 4: per-target aggregation (warp-per-edge, float4) ----------------
__global__ __launch_bounds__(128) void k_agg(float* __restrict__ out,
                                             const float* __restrict__ fb) {
    __shared__ int    sids[CHUNK];
    __shared__ float  ws[CHUNK];
    __shared__ float4 sacc[4][32];
    __shared__ float  sasum[4];
    int n = blockIdx.x, tid = threadIdx.x, lane = tid & 31, wid = tid >> 5;
    int b = g_offsets[n], e = g_offsets[n + 1];
    float M  = funkey(g_meta.amax);
    float tn = g_t[n];

    float4 q4 = *reinterpret_cast<const float4*>(&g_Q[n * D + lane * 4]);
    float4 f4 = *reinterpret_cast<const float4*>(&fb[lane * 4]);
    float4 qf = make_float4(q4.x + f4.x, q4.y + f4.y, q4.z + f4.z, q4.w + f4.w);

    float4 acc = make_float4(0.f, 0.f, 0.f, 0.f);
    float asum = 0.f;
    for (int base = b; base < e; base += CHUNK) {
        int cnt = min(e - base, CHUNK);
        __syncthreads();
        for (int i = tid; i < cnt; i += 128) {
            int sid = g_edge_src[base + i];
            sids[i] = sid;
            ws[i]   = __expf(g_s[sid] + tn - M);   // exact-max-stabilized a_exp
        }
        __syncthreads();
        for (int i = wid; i < cnt; i += 4) {
            int sid = sids[i];
            float w = ws[i];
            float4 p = *reinterpret_cast<const float4*>(&g_P[sid * D + lane * 4]);
            acc.x = fmaf(fmaxf(p.x + qf.x, 0.f), w, acc.x);
            acc.y = fmaf(fmaxf(p.y + qf.y, 0.f), w, acc.y);
            acc.z = fmaf(fmaxf(p.z + qf.z, 0.f), w, acc.z);
            acc.w = fmaf(fmaxf(p.w + qf.w, 0.f), w, acc.w);
            asum += w;
        }
    }
    sacc[wid][lane] = acc;
    if (lane == 0) sasum[wid] = asum;
    __syncthreads();

    const float* sp = reinterpret_cast<const float*>(sacc);
    float a = sp[tid] + sp[128 + tid] + sp[256 + tid] + sp[384 + tid];
    float s = sasum[0] + sasum[1] + sasum[2] + sasum[3];
    out[n * D + tid] = a / (s + EPSF);
}

// ---------------- launch ----------------
extern "C" void kernel_launch(void* const* d_in, const int* in_sizes, int n_in,
                              void* d_out, int out_size) {
    const float* x   = (const float*)d_in[0];
    const int*   src = (const int*)  d_in[2];
    const int*   tgt = (const int*)  d_in[3];
    const float* fW  = (const float*)d_in[6];
    const float* fb  = (const float*)d_in[7];
    const float* wW  = (const float*)d_in[8];
    float*       out = (float*)d_out;

    void* mp = nullptr;
    cudaGetSymbolAddress(&mp, g_meta);
    cudaMemsetAsync(mp, 0, sizeof(Meta));

    k_pre    <<<NODES / NB, 256>>>(x, fW, wW, tgt);
    k_scan   <<<1, 512>>>();
    k_scatter<<<EDGES / 256, 256>>>(src, tgt);
    k_agg    <<<NODES, 128>>>(out, fb);
}